// round 2
// baseline (speedup 1.0000x reference)
#include <cuda_runtime.h>
#include <math.h>

#define BB 2
#define NN 256
#define NODE_DIM 128
#define EDGE_DIM 256
#define HID 256
#define HH 8
#define DD 32
#define LN_EPS 1e-5f
#define OUT_EDGE_BASE (BB*NN*HID)

// ---------------- scratch (device globals; no allocations allowed) ----------
__device__ float d_h [BB*NN*HID];     // node projection (residual)
__device__ float d_q [BB*NN*HID];
__device__ float d_k [BB*NN*HID];
__device__ float d_v [BB*NN*HID];
__device__ float d_scores[BB*HH*NN*NN]; // scores -> attn (in place)
__device__ float d_am[BB*NN*NN];      // attn mean over heads
__device__ float d_ao[BB*NN*HID];     // attention output (pre-Wo)
__device__ float d_hp[BB*NN*HID];     // h_out @ Weo

// ---------------- 1. h = node @ Wn + bn ------------------------------------
__global__ void k_node_proj(const float* __restrict__ node,
                            const float* __restrict__ Wn,
                            const float* __restrict__ bn) {
    int row = blockIdx.x;          // [0, B*N)
    int c   = threadIdx.x;         // [0, HID)
    __shared__ float s[NODE_DIM];
    if (c < NODE_DIM) s[c] = node[row*NODE_DIM + c];
    __syncthreads();
    float acc = bn[c];
    #pragma unroll 8
    for (int k = 0; k < NODE_DIM; ++k) acc += s[k] * Wn[k*HID + c];
    d_h[row*HID + c] = acc;
}

// ---------------- 2. Q,K,V -------------------------------------------------
__global__ void k_qkv(const float* __restrict__ Wq, const float* __restrict__ bq,
                      const float* __restrict__ Wk, const float* __restrict__ bk,
                      const float* __restrict__ Wv, const float* __restrict__ bv) {
    int row = blockIdx.x;
    int c   = threadIdx.x;
    __shared__ float s[HID];
    s[c] = d_h[row*HID + c];
    __syncthreads();
    float aq = bq[c], ak = bk[c], av = bv[c];
    #pragma unroll 4
    for (int k = 0; k < HID; ++k) {
        float e = s[k];
        aq += e * Wq[k*HID + c];
        ak += e * Wk[k*HID + c];
        av += e * Wv[k*HID + c];
    }
    d_q[row*HID + c] = aq;
    d_k[row*HID + c] = ak;
    d_v[row*HID + c] = av;
}

// ---------------- 3. scores = QK^T / sqrt(D) --------------------------------
__global__ void k_scores() {
    int bid = blockIdx.x;                 // (b,h,n) : b*H*N + h*N + n
    int n = bid % NN;
    int h = (bid / NN) % HH;
    int b = bid / (NN * HH);
    int m = threadIdx.x;
    __shared__ float sq[DD];
    if (m < DD) sq[m] = d_q[(b*NN + n)*HID + h*DD + m];
    __syncthreads();
    const float* kr = &d_k[(b*NN + m)*HID + h*DD];
    float acc = 0.f;
    #pragma unroll
    for (int d = 0; d < DD; ++d) acc += sq[d] * kr[d];
    d_scores[bid*NN + m] = acc * 0.17677669529663687f;   // 1/sqrt(32)
}

// ---------------- 4. edge bias GEMM (THE big kernel) ------------------------
// For 32 edges (rows): p = E@Wep+bep, g = sigmoid(E@Weg+beg),
// edge_attn[row][h] = sum_d p*g ; accumulated into d_scores.
#define KC 16
__global__ void __launch_bounds__(256, 2)
k_edge_attn(const float* __restrict__ E,
            const float* __restrict__ Wep, const float* __restrict__ bep,
            const float* __restrict__ Weg, const float* __restrict__ beg) {
    __shared__ float sE [KC][32];
    __shared__ float sWp[KC][EDGE_DIM];
    __shared__ float sWg[KC][EDGE_DIM];
    __shared__ float sAcc[32][HH];

    int tid = threadIdx.x;
    int tx  = tid & 31;      // column group -> cols [tx*8, tx*8+8)
    int ty  = tid >> 5;      // row group    -> rows [ty*4, ty*4+4)
    int row0 = blockIdx.x * 32;

    float accP[4][8], accG[4][8];
    #pragma unroll
    for (int r = 0; r < 4; ++r)
        #pragma unroll
        for (int c = 0; c < 8; ++c) { accP[r][c] = 0.f; accG[r][c] = 0.f; }

    for (int kb = 0; kb < EDGE_DIM; kb += KC) {
        // E tile: 32 rows x KC
        #pragma unroll
        for (int i = 0; i < 2; ++i) {
            int lin = tid + i*256;
            int r = lin >> 4, k = lin & 15;
            sE[k][r] = E[(row0 + r)*EDGE_DIM + kb + k];
        }
        // weight tiles: KC x 256, column = tid (fully coalesced)
        #pragma unroll
        for (int k = 0; k < KC; ++k) {
            sWp[k][tid] = Wep[(kb + k)*EDGE_DIM + tid];
            sWg[k][tid] = Weg[(kb + k)*EDGE_DIM + tid];
        }
        __syncthreads();
        #pragma unroll
        for (int k = 0; k < KC; ++k) {
            float4 a  = *(const float4*)&sE [k][ty*4];
            float4 p0 = *(const float4*)&sWp[k][tx*8];
            float4 p1 = *(const float4*)&sWp[k][tx*8 + 4];
            float4 q0 = *(const float4*)&sWg[k][tx*8];
            float4 q1 = *(const float4*)&sWg[k][tx*8 + 4];
            float av[4] = {a.x, a.y, a.z, a.w};
            float pv[8] = {p0.x, p0.y, p0.z, p0.w, p1.x, p1.y, p1.z, p1.w};
            float gv[8] = {q0.x, q0.y, q0.z, q0.w, q1.x, q1.y, q1.z, q1.w};
            #pragma unroll
            for (int r = 0; r < 4; ++r)
                #pragma unroll
                for (int c = 0; c < 8; ++c) {
                    accP[r][c] += av[r] * pv[c];
                    accG[r][c] += av[r] * gv[c];
                }
        }
        __syncthreads();
    }

    // epilogue: bias + sigmoid + gated per-head reduction
    sAcc[tid >> 3][tid & 7] = 0.f;
    __syncthreads();
    int c0   = tx * 8;
    int head = c0 >> 5;     // 8 contiguous cols always within one head
    #pragma unroll
    for (int r = 0; r < 4; ++r) {
        float s = 0.f;
        #pragma unroll
        for (int c = 0; c < 8; ++c) {
            float p = accP[r][c] + bep[c0 + c];
            float g = accG[r][c] + beg[c0 + c];
            g = 1.f / (1.f + expf(-g));
            s += p * g;
        }
        atomicAdd(&sAcc[ty*4 + r][head], s);
    }
    __syncthreads();
    {
        int r = tid >> 3, h = tid & 7;
        int grow = row0 + r;                 // (b,n,m) flattened
        int m = grow & 255, n = (grow >> 8) & 255, b = grow >> 16;
        d_scores[((b*HH + h)*NN + n)*NN + m] += sAcc[r][h];
    }
}

// ---------------- 5. masked softmax (in place) -------------------------------
__global__ void k_softmax(const int* __restrict__ adj) {
    int bid = blockIdx.x;                 // (b,h,n)
    int n = bid % NN;
    int b = bid / (NN * HH);
    int m = threadIdx.x;
    float sc = d_scores[bid*NN + m];
    if (adj[(b*NN + n)*NN + m] == 0) sc = -1e9f;
    __shared__ float red[256];
    red[m] = sc; __syncthreads();
    for (int s = 128; s > 0; s >>= 1) { if (m < s) red[m] = fmaxf(red[m], red[m+s]); __syncthreads(); }
    float mx = red[0]; __syncthreads();
    float e = expf(sc - mx);
    red[m] = e; __syncthreads();
    for (int s = 128; s > 0; s >>= 1) { if (m < s) red[m] += red[m+s]; __syncthreads(); }
    d_scores[bid*NN + m] = e / red[0];
}

// ---------------- 6. attention mean over heads -------------------------------
__global__ void k_attn_mean() {
    int idx = blockIdx.x * 256 + threadIdx.x;   // (b,n,m)
    int m = idx & 255, n = (idx >> 8) & 255, b = idx >> 16;
    float s = 0.f;
    #pragma unroll
    for (int h = 0; h < HH; ++h) s += d_scores[((b*HH + h)*NN + n)*NN + m];
    d_am[idx] = s * (1.f / HH);
}

// ---------------- 7. attn_out = attn @ V -------------------------------------
__global__ void k_attn_out() {
    int row = blockIdx.x;                 // (b,n)
    int b = row >> 8;
    int n = row & 255;
    __shared__ float sA[HH][NN];          // 8KB
    for (int i = threadIdx.x; i < HH*NN; i += 256) {
        int h = i >> 8, m = i & 255;
        sA[h][m] = d_scores[((b*HH + h)*NN + n)*NN + m];
    }
    __syncthreads();
    int c = threadIdx.x;
    int h = c >> 5;
    float acc = 0.f;
    #pragma unroll 4
    for (int m = 0; m < NN; ++m) acc += sA[h][m] * d_v[(b*NN + m)*HID + c];
    d_ao[row*HID + c] = acc;
}

// ---------------- 8. h_out = LN(residual + attn_out@Wo + bo) ------------------
__global__ void k_hout(const float* __restrict__ Wo, const float* __restrict__ bo,
                       const float* __restrict__ g1, const float* __restrict__ b1,
                       float* __restrict__ out) {
    int row = blockIdx.x;
    int c   = threadIdx.x;
    __shared__ float s[HID];
    __shared__ float red[256];
    s[c] = d_ao[row*HID + c];
    __syncthreads();
    float acc = bo[c];
    #pragma unroll 4
    for (int k = 0; k < HID; ++k) acc += s[k] * Wo[k*HID + c];
    float y = acc + d_h[row*HID + c];
    red[c] = y; __syncthreads();
    for (int st = 128; st > 0; st >>= 1) { if (c < st) red[c] += red[c+st]; __syncthreads(); }
    float mean = red[0] * (1.f / HID); __syncthreads();
    float dlt = y - mean;
    red[c] = dlt * dlt; __syncthreads();
    for (int st = 128; st > 0; st >>= 1) { if (c < st) red[c] += red[c+st]; __syncthreads(); }
    float var = red[0] * (1.f / HID);
    out[row*HID + c] = (y - mean) * rsqrtf(var + LN_EPS) * g1[c] + b1[c];
}

// ---------------- 9. hp = h_out @ Weo -----------------------------------------
__global__ void k_hp(const float* __restrict__ out, const float* __restrict__ Weo) {
    int row = blockIdx.x;
    int c   = threadIdx.x;
    __shared__ float s[HID];
    s[c] = out[row*HID + c];
    __syncthreads();
    float acc = 0.f;
    #pragma unroll 4
    for (int k = 0; k < HID; ++k) acc += s[k] * Weo[k*EDGE_DIM + c];
    d_hp[row*EDGE_DIM + c] = acc;
}

// ---------------- 10. edge_out = LN(E + am*0.5*(hp_n+hp_m) + beo) --------------
// one warp per edge, warp-shuffle LN (no block barriers)
__global__ void k_edge_out(const float* __restrict__ E,
                           const float* __restrict__ beo,
                           const float* __restrict__ g2,
                           const float* __restrict__ b2,
                           float* __restrict__ out) {
    int w = blockIdx.x * 8 + (threadIdx.x >> 5);   // edge (b,n,m) flattened
    int lane = threadIdx.x & 31;
    int m = w & 255, n = (w >> 8) & 255, b = w >> 16;
    float am = d_am[w] * 0.5f;
    const float* Er = &E[(size_t)w * EDGE_DIM];
    const float* hn = &d_hp[(b*NN + n)*EDGE_DIM];
    const float* hm = &d_hp[(b*NN + m)*EDGE_DIM];
    float x[8];
    float s = 0.f, s2 = 0.f;
    #pragma unroll
    for (int j = 0; j < 8; ++j) {
        int c = j*32 + lane;
        float v = Er[c] + am * (hn[c] + hm[c]) + beo[c];
        x[j] = v; s += v; s2 += v * v;
    }
    #pragma unroll
    for (int o = 16; o > 0; o >>= 1) {
        s  += __shfl_xor_sync(0xffffffffu, s,  o);
        s2 += __shfl_xor_sync(0xffffffffu, s2, o);
    }
    float mean = s * (1.f / EDGE_DIM);
    float var  = s2 * (1.f / EDGE_DIM) - mean * mean;
    float rinv = rsqrtf(var + LN_EPS);
    float* op = &out[OUT_EDGE_BASE + (size_t)w * EDGE_DIM];
    #pragma unroll
    for (int j = 0; j < 8; ++j) {
        int c = j*32 + lane;
        op[c] = (x[j] - mean) * rinv * g2[c] + b2[c];
    }
}

// ---------------- launch ------------------------------------------------------
extern "C" void kernel_launch(void* const* d_in, const int* in_sizes, int n_in,
                              void* d_out, int out_size) {
    const float* node = (const float*)d_in[0];
    const float* E    = (const float*)d_in[1];
    const int*   adj  = (const int*)  d_in[2];
    const float* Wn  = (const float*)d_in[3];  const float* bn  = (const float*)d_in[4];
    const float* Wq  = (const float*)d_in[5];  const float* bq  = (const float*)d_in[6];
    const float* Wk  = (const float*)d_in[7];  const float* bk  = (const float*)d_in[8];
    const float* Wv  = (const float*)d_in[9];  const float* bv  = (const float*)d_in[10];
    const float* Wep = (const float*)d_in[11]; const float* bep = (const float*)d_in[12];
    const float* Weg = (const float*)d_in[13]; const float* beg = (const float*)d_in[14];
    const float* Wo  = (const float*)d_in[15]; const float* bo  = (const float*)d_in[16];
    const float* Weo = (const float*)d_in[17]; const float* beo = (const float*)d_in[18];
    const float* g1  = (const float*)d_in[19]; const float* b1  = (const float*)d_in[20];
    const float* g2  = (const float*)d_in[21]; const float* b2  = (const float*)d_in[22];
    float* out = (float*)d_out;

    k_node_proj<<<BB*NN, HID>>>(node, Wn, bn);
    k_qkv      <<<BB*NN, HID>>>(Wq, bq, Wk, bk, Wv, bv);
    k_scores   <<<BB*HH*NN, NN>>>();
    k_edge_attn<<<BB*NN*NN/32, 256>>>(E, Wep, bep, Weg, beg);
    k_softmax  <<<BB*HH*NN, NN>>>(adj);
    k_attn_mean<<<BB*NN*NN/256, 256>>>();
    k_attn_out <<<BB*NN, HID>>>();
    k_hout     <<<BB*NN, HID>>>(Wo, bo, g1, b1, out);
    k_hp       <<<BB*NN, EDGE_DIM>>>(out, Weo);
    k_edge_out <<<BB*NN*NN/8, 256>>>(E, beo, g2, b2, out);
}

// round 4
// speedup vs baseline: 2.1106x; 2.1106x over previous
#include <cuda_runtime.h>
#include <cstdint>
#include <math.h>

#define BB 2
#define NN 256
#define NODE_DIM 128
#define EDGE_DIM 256
#define HID 256
#define HH 8
#define DD 32
#define LN_EPS 1e-5f
#define OUT_EDGE_BASE (BB*NN*HID)

// ---------------- scratch (device globals) ----------------------------------
__device__ float d_h [BB*NN*HID];
__device__ float d_q [BB*NN*HID];
__device__ float d_k [BB*NN*HID];
__device__ float d_v [BB*NN*HID];
__device__ float d_scores[BB*HH*NN*NN];
__device__ float d_am[BB*NN*NN];
__device__ float d_ao[BB*NN*HID];
__device__ float d_hp[BB*NN*HID];
__device__ __align__(16) float d_WpT[HID*EDGE_DIM];   // [n][k], tf32-rounded bits
__device__ __align__(16) float d_WgT[HID*EDGE_DIM];   // [n][k], tf32-rounded bits

// ---------------- PTX helpers (sm_80-era only; no tcgen05) -------------------
__device__ __forceinline__ uint32_t smem_u32(const void* p) {
    uint32_t a;
    asm("{ .reg .u64 t; cvta.to.shared.u64 t, %1; cvt.u32.u64 %0, t; }" : "=r"(a) : "l"(p));
    return a;
}
__device__ __forceinline__ void cp_async16(uint32_t dst, const void* src) {
    asm volatile("cp.async.cg.shared.global [%0], [%1], 16;" :: "r"(dst), "l"(src));
}
#define CP_COMMIT() asm volatile("cp.async.commit_group;" ::: "memory")
#define CP_WAIT(n)  asm volatile("cp.async.wait_group %0;" :: "n"(n) : "memory")

__device__ __forceinline__ void mma_tf32(float d[4], const uint32_t a[4],
                                         uint32_t b0, uint32_t b1) {
    asm volatile(
        "mma.sync.aligned.m16n8k8.row.col.f32.tf32.tf32.f32 "
        "{%0,%1,%2,%3}, {%4,%5,%6,%7}, {%8,%9}, {%0,%1,%2,%3};"
        : "+f"(d[0]), "+f"(d[1]), "+f"(d[2]), "+f"(d[3])
        : "r"(a[0]), "r"(a[1]), "r"(a[2]), "r"(a[3]), "r"(b0), "r"(b1));
}

// ---------------- 0. weight transpose + tf32 round ---------------------------
__global__ void k_wT(const float* __restrict__ Wep, const float* __restrict__ Weg) {
    __shared__ float t[32][33];
    const float* W = blockIdx.z ? Weg : Wep;
    float* O = blockIdx.z ? d_WgT : d_WpT;
    int n0 = blockIdx.x * 32, k0 = blockIdx.y * 32;
    t[threadIdx.y][threadIdx.x] = W[(k0 + threadIdx.y) * EDGE_DIM + n0 + threadIdx.x];
    __syncthreads();
    float v = t[threadIdx.x][threadIdx.y];      // = W[k0+tx][n0+ty]
    uint32_t u;
    asm("cvt.rna.tf32.f32 %0, %1;" : "=r"(u) : "f"(v));
    O[(n0 + threadIdx.y) * EDGE_DIM + k0 + threadIdx.x] = __uint_as_float(u);
}

// ---------------- 1. h = node @ Wn + bn (8 rows/block) -----------------------
__global__ void k_node_proj(const float* __restrict__ node,
                            const float* __restrict__ Wn,
                            const float* __restrict__ bn) {
    int r0 = blockIdx.x * 8;
    __shared__ float s[8][NODE_DIM];
    for (int i = threadIdx.x; i < 8 * NODE_DIM; i += 256)
        s[i >> 7][i & 127] = node[(r0 + (i >> 7)) * NODE_DIM + (i & 127)];
    __syncthreads();
    int c = threadIdx.x;
    float acc[8]; float bb = bn[c];
    #pragma unroll
    for (int r = 0; r < 8; ++r) acc[r] = bb;
    #pragma unroll 4
    for (int k = 0; k < NODE_DIM; ++k) {
        float w = Wn[k * HID + c];
        #pragma unroll
        for (int r = 0; r < 8; ++r) acc[r] += s[r][k] * w;
    }
    #pragma unroll
    for (int r = 0; r < 8; ++r) d_h[(r0 + r) * HID + c] = acc[r];
}

// ---------------- 2. Q,K,V (8 rows/block) ------------------------------------
__global__ void k_qkv(const float* __restrict__ Wq, const float* __restrict__ bq,
                      const float* __restrict__ Wk, const float* __restrict__ bk,
                      const float* __restrict__ Wv, const float* __restrict__ bv) {
    int r0 = blockIdx.x * 8;
    __shared__ float s[8][HID];
    for (int i = threadIdx.x; i < 8 * HID; i += 256)
        s[i >> 8][i & 255] = d_h[(r0 + (i >> 8)) * HID + (i & 255)];
    __syncthreads();
    int c = threadIdx.x;
    float aq[8], ak[8], av[8];
    float bq0 = bq[c], bk0 = bk[c], bv0 = bv[c];
    #pragma unroll
    for (int r = 0; r < 8; ++r) { aq[r] = bq0; ak[r] = bk0; av[r] = bv0; }
    #pragma unroll 2
    for (int k = 0; k < HID; ++k) {
        float wq = Wq[k * HID + c], wk = Wk[k * HID + c], wv = Wv[k * HID + c];
        #pragma unroll
        for (int r = 0; r < 8; ++r) {
            float e = s[r][k];
            aq[r] += e * wq; ak[r] += e * wk; av[r] += e * wv;
        }
    }
    #pragma unroll
    for (int r = 0; r < 8; ++r) {
        d_q[(r0 + r) * HID + c] = aq[r];
        d_k[(r0 + r) * HID + c] = ak[r];
        d_v[(r0 + r) * HID + c] = av[r];
    }
}

// ---------------- 3. scores = QK^T / sqrt(D) ---------------------------------
__global__ void k_scores() {
    int bid = blockIdx.x;                 // (b,h,n)
    int n = bid % NN;
    int h = (bid / NN) % HH;
    int b = bid / (NN * HH);
    int m = threadIdx.x;
    __shared__ float sq[DD];
    if (m < DD) sq[m] = d_q[(b * NN + n) * HID + h * DD + m];
    __syncthreads();
    const float* kr = &d_k[(b * NN + m) * HID + h * DD];
    float acc = 0.f;
    #pragma unroll
    for (int d = 0; d < DD; ++d) acc += sq[d] * kr[d];
    d_scores[bid * NN + m] = acc * 0.17677669529663687f;
}

// ---------------- 4. edge bias via mma.sync tf32 ------------------------------
// Per CTA: M=256 edge rows, one head: N=64 (32 P + 32 G), K=256 in chunks of 32.
// smem float offsets
#define SA_STRIDE 36
#define SA_BUF    (256*SA_STRIDE)        // 9216 floats per buffer
#define OFF_BP    (2*SA_BUF)             // 18432
#define SB_STRIDE 260
#define OFF_BG    (OFF_BP + 32*SB_STRIDE)  // 26752
#define OFF_BIAS  (OFF_BG + 32*SB_STRIDE)  // 35072
#define SMEM_FLOATS (OFF_BIAS + 64)        // 35136
#define SMEM_BYTES  (SMEM_FLOATS*4)        // 140544

__global__ void __launch_bounds__(256, 1)
k_edge_attn_mma(const float* __restrict__ E,
                const float* __restrict__ bep, const float* __restrict__ beg) {
    extern __shared__ float sm[];
    const int tid = threadIdx.x;
    const int wid = tid >> 5, lane = tid & 31;
    const int tig = lane & 3, grp = lane >> 2;
    const int h = blockIdx.x;
    const int row0 = blockIdx.y * 256;

    float* sBp = sm + OFF_BP;
    float* sBg = sm + OFF_BG;
    float* sbias = sm + OFF_BIAS;
    uint32_t sA_addr = smem_u32(sm);

    // one-time: head's weight slices + biases into smem
    #pragma unroll
    for (int i = 0; i < 8; ++i) {
        int lin = tid + i * 256;
        int n = lin >> 6, q = lin & 63;
        *(float4*)&sBp[n * SB_STRIDE + q * 4] =
            *(const float4*)&d_WpT[(h * 32 + n) * EDGE_DIM + q * 4];
        *(float4*)&sBg[n * SB_STRIDE + q * 4] =
            *(const float4*)&d_WgT[(h * 32 + n) * EDGE_DIM + q * 4];
    }
    if (tid < 32) {
        sbias[tid]      = bep[h * 32 + tid];
        sbias[32 + tid] = beg[h * 32 + tid];
    }

    float d[2][8][4];
    #pragma unroll
    for (int m = 0; m < 2; ++m)
        #pragma unroll
        for (int j = 0; j < 8; ++j)
            #pragma unroll
            for (int e = 0; e < 4; ++e) d[m][j][e] = 0.f;

    // prefetch chunk 0
    {
        #pragma unroll
        for (int i = 0; i < 8; ++i) {
            int lin = tid + i * 256;
            int r = lin >> 3, q = lin & 7;
            cp_async16(sA_addr + (r * SA_STRIDE + q * 4) * 4,
                       &E[(size_t)(row0 + r) * EDGE_DIM + q * 4]);
        }
        CP_COMMIT();
    }

    #pragma unroll 1
    for (int c = 0; c < 8; ++c) {
        int buf = c & 1;
        if (c < 7) {
            int nb = buf ^ 1;
            #pragma unroll
            for (int i = 0; i < 8; ++i) {
                int lin = tid + i * 256;
                int r = lin >> 3, q = lin & 7;
                cp_async16(sA_addr + (nb * SA_BUF + r * SA_STRIDE + q * 4) * 4,
                           &E[(size_t)(row0 + r) * EDGE_DIM + (c + 1) * 32 + q * 4]);
            }
            CP_COMMIT();
            CP_WAIT(1);
        } else {
            CP_WAIT(0);
        }
        __syncthreads();

        const float* Ab = sm + buf * SA_BUF + (wid * 32) * SA_STRIDE;
        #pragma unroll
        for (int k8 = 0; k8 < 4; ++k8) {
            int kA = k8 * 8 + tig;
            uint32_t a[2][4];
            #pragma unroll
            for (int m = 0; m < 2; ++m) {
                int rb = (m * 16 + grp) * SA_STRIDE;
                a[m][0] = __float_as_uint(Ab[rb + kA]);
                a[m][1] = __float_as_uint(Ab[rb + 8 * SA_STRIDE + kA]);
                a[m][2] = __float_as_uint(Ab[rb + kA + 4]);
                a[m][3] = __float_as_uint(Ab[rb + 8 * SA_STRIDE + kA + 4]);
            }
            int kB = c * 32 + k8 * 8 + tig;
            #pragma unroll
            for (int j = 0; j < 8; ++j) {
                const float* Bm = (j < 4) ? sBp : sBg;
                int nb = ((j & 3) * 8 + grp) * SB_STRIDE;
                uint32_t b0 = __float_as_uint(Bm[nb + kB]);
                uint32_t b1 = __float_as_uint(Bm[nb + kB + 4]);
                mma_tf32(d[0][j], a[0], b0, b1);
                mma_tf32(d[1][j], a[1], b0, b1);
            }
        }
        __syncthreads();
    }

    // epilogue: bias + sigmoid + gated reduce over the head's 32 dims
    float rs0[2], rs1[2];
    #pragma unroll
    for (int m = 0; m < 2; ++m) {
        float s0 = 0.f, s1 = 0.f;
        #pragma unroll
        for (int j = 0; j < 4; ++j) {
            #pragma unroll
            for (int e = 0; e < 2; ++e) {
                int cl = j * 8 + tig * 2 + e;
                float bp = sbias[cl], bg = sbias[32 + cl];
                float p0 = d[m][j][e]     + bp;
                float g0 = d[m][j + 4][e] + bg;
                s0 += p0 / (1.f + expf(-g0));
                float p1 = d[m][j][e + 2]     + bp;
                float g1 = d[m][j + 4][e + 2] + bg;
                s1 += p1 / (1.f + expf(-g1));
            }
        }
        s0 += __shfl_xor_sync(0xffffffffu, s0, 1);
        s0 += __shfl_xor_sync(0xffffffffu, s0, 2);
        s1 += __shfl_xor_sync(0xffffffffu, s1, 1);
        s1 += __shfl_xor_sync(0xffffffffu, s1, 2);
        rs0[m] = s0; rs1[m] = s1;
    }
    if (tig == 0) {
        #pragma unroll
        for (int m = 0; m < 2; ++m) {
            #pragma unroll
            for (int rr = 0; rr < 2; ++rr) {
                int row = row0 + wid * 32 + m * 16 + grp + rr * 8;
                int mm = row & 255, nn_ = (row >> 8) & 255, b = row >> 16;
                float v = rr ? rs1[m] : rs0[m];
                d_scores[(((size_t)b * HH + h) * NN + nn_) * NN + mm] += v;
            }
        }
    }
}

// ---------------- 5. masked softmax ------------------------------------------
__global__ void k_softmax(const int* __restrict__ adj) {
    int bid = blockIdx.x;
    int n = bid % NN;
    int b = bid / (NN * HH);
    int m = threadIdx.x;
    float sc = d_scores[bid * NN + m];
    if (adj[(b * NN + n) * NN + m] == 0) sc = -1e9f;
    __shared__ float red[256];
    red[m] = sc; __syncthreads();
    for (int s = 128; s > 0; s >>= 1) { if (m < s) red[m] = fmaxf(red[m], red[m + s]); __syncthreads(); }
    float mx = red[0]; __syncthreads();
    float e = expf(sc - mx);
    red[m] = e; __syncthreads();
    for (int s = 128; s > 0; s >>= 1) { if (m < s) red[m] += red[m + s]; __syncthreads(); }
    d_scores[bid * NN + m] = e / red[0];
}

// ---------------- 6. attention mean over heads -------------------------------
__global__ void k_attn_mean() {
    int idx = blockIdx.x * 256 + threadIdx.x;
    int m = idx & 255, n = (idx >> 8) & 255, b = idx >> 16;
    float s = 0.f;
    #pragma unroll
    for (int h = 0; h < HH; ++h) s += d_scores[((b * HH + h) * NN + n) * NN + m];
    d_am[idx] = s * (1.f / HH);
}

// ---------------- 7. attn_out = attn @ V -------------------------------------
__global__ void k_attn_out() {
    int row = blockIdx.x;
    int b = row >> 8;
    int n = row & 255;
    __shared__ float sA[HH][NN];
    for (int i = threadIdx.x; i < HH * NN; i += 256) {
        int h = i >> 8, m = i & 255;
        sA[h][m] = d_scores[((b * HH + h) * NN + n) * NN + m];
    }
    __syncthreads();
    int c = threadIdx.x;
    int h = c >> 5;
    float acc = 0.f;
    #pragma unroll 4
    for (int m = 0; m < NN; ++m) acc += sA[h][m] * d_v[(b * NN + m) * HID + c];
    d_ao[row * HID + c] = acc;
}

// ---------------- 8. h_out = LN(residual + attn_out@Wo + bo) ------------------
__global__ void k_hout(const float* __restrict__ Wo, const float* __restrict__ bo,
                       const float* __restrict__ g1, const float* __restrict__ b1,
                       float* __restrict__ out) {
    int row = blockIdx.x;
    int c = threadIdx.x;
    __shared__ float s[HID];
    __shared__ float red[256];
    s[c] = d_ao[row * HID + c];
    __syncthreads();
    float acc = bo[c];
    #pragma unroll 4
    for (int k = 0; k < HID; ++k) acc += s[k] * Wo[k * HID + c];
    float y = acc + d_h[row * HID + c];
    red[c] = y; __syncthreads();
    for (int st = 128; st > 0; st >>= 1) { if (c < st) red[c] += red[c + st]; __syncthreads(); }
    float mean = red[0] * (1.f / HID); __syncthreads();
    float dlt = y - mean;
    red[c] = dlt * dlt; __syncthreads();
    for (int st = 128; st > 0; st >>= 1) { if (c < st) red[c] += red[c + st]; __syncthreads(); }
    float var = red[0] * (1.f / HID);
    out[row * HID + c] = (y - mean) * rsqrtf(var + LN_EPS) * g1[c] + b1[c];
}

// ---------------- 9. hp = h_out @ Weo (8 rows/block) --------------------------
__global__ void k_hp(const float* __restrict__ out, const float* __restrict__ Weo) {
    int r0 = blockIdx.x * 8;
    __shared__ float s[8][HID];
    for (int i = threadIdx.x; i < 8 * HID; i += 256)
        s[i >> 8][i & 255] = out[(r0 + (i >> 8)) * HID + (i & 255)];
    __syncthreads();
    int c = threadIdx.x;
    float acc[8];
    #pragma unroll
    for (int r = 0; r < 8; ++r) acc[r] = 0.f;
    #pragma unroll 2
    for (int k = 0; k < HID; ++k) {
        float w = Weo[k * EDGE_DIM + c];
        #pragma unroll
        for (int r = 0; r < 8; ++r) acc[r] += s[r][k] * w;
    }
    #pragma unroll
    for (int r = 0; r < 8; ++r) d_hp[(r0 + r) * EDGE_DIM + c] = acc[r];
}

// ---------------- 10. edge_out ------------------------------------------------
__global__ void k_edge_out(const float* __restrict__ E,
                           const float* __restrict__ beo,
                           const float* __restrict__ g2,
                           const float* __restrict__ b2,
                           float* __restrict__ out) {
    int w = blockIdx.x * 8 + (threadIdx.x >> 5);
    int lane = threadIdx.x & 31;
    int m = w & 255, n = (w >> 8) & 255, b = w >> 16;
    float am = d_am[w] * 0.5f;
    const float* Er = &E[(size_t)w * EDGE_DIM];
    const float* hn = &d_hp[(b * NN + n) * EDGE_DIM];
    const float* hm = &d_hp[(b * NN + m) * EDGE_DIM];
    float x[8];
    float s = 0.f, s2 = 0.f;
    #pragma unroll
    for (int j = 0; j < 8; ++j) {
        int c = j * 32 + lane;
        float v = Er[c] + am * (hn[c] + hm[c]) + beo[c];
        x[j] = v; s += v; s2 += v * v;
    }
    #pragma unroll
    for (int o = 16; o > 0; o >>= 1) {
        s  += __shfl_xor_sync(0xffffffffu, s,  o);
        s2 += __shfl_xor_sync(0xffffffffu, s2, o);
    }
    float mean = s * (1.f / EDGE_DIM);
    float var  = s2 * (1.f / EDGE_DIM) - mean * mean;
    float rinv = rsqrtf(var + LN_EPS);
    float* op = &out[OUT_EDGE_BASE + (size_t)w * EDGE_DIM];
    #pragma unroll
    for (int j = 0; j < 8; ++j) {
        int c = j * 32 + lane;
        op[c] = (x[j] - mean) * rinv * g2[c] + b2[c];
    }
}

// ---------------- launch ------------------------------------------------------
extern "C" void kernel_launch(void* const* d_in, const int* in_sizes, int n_in,
                              void* d_out, int out_size) {
    const float* node = (const float*)d_in[0];
    const float* E    = (const float*)d_in[1];
    const int*   adj  = (const int*)  d_in[2];
    const float* Wn  = (const float*)d_in[3];  const float* bn  = (const float*)d_in[4];
    const float* Wq  = (const float*)d_in[5];  const float* bq  = (const float*)d_in[6];
    const float* Wk  = (const float*)d_in[7];  const float* bk  = (const float*)d_in[8];
    const float* Wv  = (const float*)d_in[9];  const float* bv  = (const float*)d_in[10];
    const float* Wep = (const float*)d_in[11]; const float* bep = (const float*)d_in[12];
    const float* Weg = (const float*)d_in[13]; const float* beg = (const float*)d_in[14];
    const float* Wo  = (const float*)d_in[15]; const float* bo  = (const float*)d_in[16];
    const float* Weo = (const float*)d_in[17]; const float* beo = (const float*)d_in[18];
    const float* g1  = (const float*)d_in[19]; const float* b1  = (const float*)d_in[20];
    const float* g2  = (const float*)d_in[21]; const float* b2  = (const float*)d_in[22];
    float* out = (float*)d_out;

    cudaFuncSetAttribute(k_edge_attn_mma,
                         cudaFuncAttributeMaxDynamicSharedMemorySize, SMEM_BYTES);

    k_wT        <<<dim3(8, 8, 2), dim3(32, 32)>>>(Wep, Weg);
    k_node_proj <<<BB*NN/8, 256>>>(node, Wn, bn);
    k_qkv       <<<BB*NN/8, 256>>>(Wq, bq, Wk, bk, Wv, bv);
    k_scores    <<<BB*HH*NN, NN>>>();
    k_edge_attn_mma<<<dim3(HH, BB*NN*NN/256), 256, SMEM_BYTES>>>(E, bep, beg);
    k_softmax   <<<BB*HH*NN, NN>>>(adj);
    k_attn_mean <<<BB*NN*NN/256, 256>>>();
    k_attn_out  <<<BB*NN, HID>>>();
    k_hout      <<<BB*NN, HID>>>(Wo, bo, g1, b1, out);
    k_hp        <<<BB*NN/8, 256>>>(out, Weo);
    k_edge_out  <<<BB*NN*NN/8, 256>>>(E, beo, g2, b2, out);
}

// round 5
// speedup vs baseline: 2.1155x; 1.0023x over previous
#include <cuda_runtime.h>
#include <cstdint>
#include <math.h>

#define BB 2
#define NN 256
#define NODE_DIM 128
#define EDGE_DIM 256
#define HID 256
#define HH 8
#define DD 32
#define LN_EPS 1e-5f
#define OUT_EDGE_BASE (BB*NN*HID)

// ---------------- scratch (device globals) ----------------------------------
__device__ float d_h [BB*NN*HID];
__device__ float d_q [BB*NN*HID];
__device__ float d_k [BB*NN*HID];
__device__ float d_v [BB*NN*HID];
__device__ float d_scores[BB*HH*NN*NN];
__device__ float d_am[BB*NN*NN];
__device__ float d_ao[BB*NN*HID];
__device__ float d_hp[BB*NN*HID];
__device__ __align__(16) float d_WpT[HID*EDGE_DIM];   // [n][k], tf32-rounded bits
__device__ __align__(16) float d_WgT[HID*EDGE_DIM];   // [n][k], tf32-rounded bits

// ---------------- PTX helpers (sm_80-era only; no tcgen05) -------------------
__device__ __forceinline__ uint32_t smem_u32(const void* p) {
    uint32_t a;
    asm("{ .reg .u64 t; cvta.to.shared.u64 t, %1; cvt.u32.u64 %0, t; }" : "=r"(a) : "l"(p));
    return a;
}
__device__ __forceinline__ void cp_async16(uint32_t dst, const void* src) {
    asm volatile("cp.async.cg.shared.global [%0], [%1], 16;" :: "r"(dst), "l"(src));
}
#define CP_COMMIT() asm volatile("cp.async.commit_group;" ::: "memory")
#define CP_WAIT(n)  asm volatile("cp.async.wait_group %0;" :: "n"(n) : "memory")

__device__ __forceinline__ void mma_tf32(float d[4], const uint32_t a[4],
                                         uint32_t b0, uint32_t b1) {
    asm volatile(
        "mma.sync.aligned.m16n8k8.row.col.f32.tf32.tf32.f32 "
        "{%0,%1,%2,%3}, {%4,%5,%6,%7}, {%8,%9}, {%0,%1,%2,%3};"
        : "+f"(d[0]), "+f"(d[1]), "+f"(d[2]), "+f"(d[3])
        : "r"(a[0]), "r"(a[1]), "r"(a[2]), "r"(a[3]), "r"(b0), "r"(b1));
}

// ---------------- 0. weight transpose + tf32 round ---------------------------
__global__ void k_wT(const float* __restrict__ Wep, const float* __restrict__ Weg) {
    __shared__ float t[32][33];
    const float* W = blockIdx.z ? Weg : Wep;
    float* O = blockIdx.z ? d_WgT : d_WpT;
    int n0 = blockIdx.x * 32, k0 = blockIdx.y * 32;
    t[threadIdx.y][threadIdx.x] = W[(k0 + threadIdx.y) * EDGE_DIM + n0 + threadIdx.x];
    __syncthreads();
    float v = t[threadIdx.x][threadIdx.y];      // = W[k0+tx][n0+ty]
    uint32_t u;
    asm("cvt.rna.tf32.f32 %0, %1;" : "=r"(u) : "f"(v));
    O[(n0 + threadIdx.y) * EDGE_DIM + k0 + threadIdx.x] = __uint_as_float(u);
}

// ---------------- 1. h = node @ Wn + bn (8 rows/block) -----------------------
__global__ void k_node_proj(const float* __restrict__ node,
                            const float* __restrict__ Wn,
                            const float* __restrict__ bn) {
    int r0 = blockIdx.x * 8;
    __shared__ float s[8][NODE_DIM];
    for (int i = threadIdx.x; i < 8 * NODE_DIM; i += 256)
        s[i >> 7][i & 127] = node[(r0 + (i >> 7)) * NODE_DIM + (i & 127)];
    __syncthreads();
    int c = threadIdx.x;
    float acc[8]; float bb = bn[c];
    #pragma unroll
    for (int r = 0; r < 8; ++r) acc[r] = bb;
    #pragma unroll 4
    for (int k = 0; k < NODE_DIM; ++k) {
        float w = Wn[k * HID + c];
        #pragma unroll
        for (int r = 0; r < 8; ++r) acc[r] += s[r][k] * w;
    }
    #pragma unroll
    for (int r = 0; r < 8; ++r) d_h[(r0 + r) * HID + c] = acc[r];
}

// ---------------- 2. Q,K,V (8 rows/block) ------------------------------------
__global__ void k_qkv(const float* __restrict__ Wq, const float* __restrict__ bq,
                      const float* __restrict__ Wk, const float* __restrict__ bk,
                      const float* __restrict__ Wv, const float* __restrict__ bv) {
    int r0 = blockIdx.x * 8;
    __shared__ float s[8][HID];
    for (int i = threadIdx.x; i < 8 * HID; i += 256)
        s[i >> 8][i & 255] = d_h[(r0 + (i >> 8)) * HID + (i & 255)];
    __syncthreads();
    int c = threadIdx.x;
    float aq[8], ak[8], av[8];
    float bq0 = bq[c], bk0 = bk[c], bv0 = bv[c];
    #pragma unroll
    for (int r = 0; r < 8; ++r) { aq[r] = bq0; ak[r] = bk0; av[r] = bv0; }
    #pragma unroll 2
    for (int k = 0; k < HID; ++k) {
        float wq = Wq[k * HID + c], wk = Wk[k * HID + c], wv = Wv[k * HID + c];
        #pragma unroll
        for (int r = 0; r < 8; ++r) {
            float e = s[r][k];
            aq[r] += e * wq; ak[r] += e * wk; av[r] += e * wv;
        }
    }
    #pragma unroll
    for (int r = 0; r < 8; ++r) {
        d_q[(r0 + r) * HID + c] = aq[r];
        d_k[(r0 + r) * HID + c] = ak[r];
        d_v[(r0 + r) * HID + c] = av[r];
    }
}

// ---------------- 3. scores = QK^T / sqrt(D) ---------------------------------
__global__ void k_scores() {
    int bid = blockIdx.x;                 // (b,h,n)
    int n = bid % NN;
    int h = (bid / NN) % HH;
    int b = bid / (NN * HH);
    int m = threadIdx.x;
    __shared__ float sq[DD];
    if (m < DD) sq[m] = d_q[(b * NN + n) * HID + h * DD + m];
    __syncthreads();
    const float* kr = &d_k[(b * NN + m) * HID + h * DD];
    float acc = 0.f;
    #pragma unroll
    for (int d = 0; d < DD; ++d) acc += sq[d] * kr[d];
    d_scores[bid * NN + m] = acc * 0.17677669529663687f;
}

// ---------------- 4. edge bias via mma.sync tf32 ------------------------------
// Per CTA: M=256 edge rows, one head: N=64 (32 P + 32 G), K=256 in chunks of 32.
// smem float offsets
#define SA_STRIDE 36
#define SA_BUF    (256*SA_STRIDE)        // 9216 floats per buffer
#define OFF_BP    (2*SA_BUF)             // 18432
#define SB_STRIDE 260
#define OFF_BG    (OFF_BP + 32*SB_STRIDE)  // 26752
#define OFF_BIAS  (OFF_BG + 32*SB_STRIDE)  // 35072
#define SMEM_FLOATS (OFF_BIAS + 64)        // 35136
#define SMEM_BYTES  (SMEM_FLOATS*4)        // 140544

__global__ void __launch_bounds__(256, 1)
k_edge_attn_mma(const float* __restrict__ E,
                const float* __restrict__ bep, const float* __restrict__ beg) {
    extern __shared__ float sm[];
    const int tid = threadIdx.x;
    const int wid = tid >> 5, lane = tid & 31;
    const int tig = lane & 3, grp = lane >> 2;
    const int h = blockIdx.x;
    const int row0 = blockIdx.y * 256;

    float* sBp = sm + OFF_BP;
    float* sBg = sm + OFF_BG;
    float* sbias = sm + OFF_BIAS;
    uint32_t sA_addr = smem_u32(sm);

    // one-time: head's weight slices + biases into smem
    #pragma unroll
    for (int i = 0; i < 8; ++i) {
        int lin = tid + i * 256;
        int n = lin >> 6, q = lin & 63;
        *(float4*)&sBp[n * SB_STRIDE + q * 4] =
            *(const float4*)&d_WpT[(h * 32 + n) * EDGE_DIM + q * 4];
        *(float4*)&sBg[n * SB_STRIDE + q * 4] =
            *(const float4*)&d_WgT[(h * 32 + n) * EDGE_DIM + q * 4];
    }
    if (tid < 32) {
        sbias[tid]      = bep[h * 32 + tid];
        sbias[32 + tid] = beg[h * 32 + tid];
    }

    float d[2][8][4];
    #pragma unroll
    for (int m = 0; m < 2; ++m)
        #pragma unroll
        for (int j = 0; j < 8; ++j)
            #pragma unroll
            for (int e = 0; e < 4; ++e) d[m][j][e] = 0.f;

    // prefetch chunk 0
    {
        #pragma unroll
        for (int i = 0; i < 8; ++i) {
            int lin = tid + i * 256;
            int r = lin >> 3, q = lin & 7;
            cp_async16(sA_addr + (r * SA_STRIDE + q * 4) * 4,
                       &E[(size_t)(row0 + r) * EDGE_DIM + q * 4]);
        }
        CP_COMMIT();
    }

    #pragma unroll 1
    for (int c = 0; c < 8; ++c) {
        int buf = c & 1;
        if (c < 7) {
            int nb = buf ^ 1;
            #pragma unroll
            for (int i = 0; i < 8; ++i) {
                int lin = tid + i * 256;
                int r = lin >> 3, q = lin & 7;
                cp_async16(sA_addr + (nb * SA_BUF + r * SA_STRIDE + q * 4) * 4,
                           &E[(size_t)(row0 + r) * EDGE_DIM + (c + 1) * 32 + q * 4]);
            }
            CP_COMMIT();
            CP_WAIT(1);
        } else {
            CP_WAIT(0);
        }
        __syncthreads();

        const float* Ab = sm + buf * SA_BUF + (wid * 32) * SA_STRIDE;
        #pragma unroll
        for (int k8 = 0; k8 < 4; ++k8) {
            int kA = k8 * 8 + tig;
            uint32_t a[2][4];
            #pragma unroll
            for (int m = 0; m < 2; ++m) {
                int rb = (m * 16 + grp) * SA_STRIDE;
                a[m][0] = __float_as_uint(Ab[rb + kA]);
                a[m][1] = __float_as_uint(Ab[rb + 8 * SA_STRIDE + kA]);
                a[m][2] = __float_as_uint(Ab[rb + kA + 4]);
                a[m][3] = __float_as_uint(Ab[rb + 8 * SA_STRIDE + kA + 4]);
            }
            int kB = c * 32 + k8 * 8 + tig;
            #pragma unroll
            for (int j = 0; j < 8; ++j) {
                const float* Bm = (j < 4) ? sBp : sBg;
                int nb = ((j & 3) * 8 + grp) * SB_STRIDE;
                uint32_t b0 = __float_as_uint(Bm[nb + kB]);
                uint32_t b1 = __float_as_uint(Bm[nb + kB + 4]);
                mma_tf32(d[0][j], a[0], b0, b1);
                mma_tf32(d[1][j], a[1], b0, b1);
            }
        }
        __syncthreads();
    }

    // epilogue: bias + sigmoid + gated reduce over the head's 32 dims
    float rs0[2], rs1[2];
    #pragma unroll
    for (int m = 0; m < 2; ++m) {
        float s0 = 0.f, s1 = 0.f;
        #pragma unroll
        for (int j = 0; j < 4; ++j) {
            #pragma unroll
            for (int e = 0; e < 2; ++e) {
                int cl = j * 8 + tig * 2 + e;
                float bp = sbias[cl], bg = sbias[32 + cl];
                float p0 = d[m][j][e]     + bp;
                float g0 = d[m][j + 4][e] + bg;
                s0 += p0 / (1.f + expf(-g0));
                float p1 = d[m][j][e + 2]     + bp;
                float g1 = d[m][j + 4][e + 2] + bg;
                s1 += p1 / (1.f + expf(-g1));
            }
        }
        s0 += __shfl_xor_sync(0xffffffffu, s0, 1);
        s0 += __shfl_xor_sync(0xffffffffu, s0, 2);
        s1 += __shfl_xor_sync(0xffffffffu, s1, 1);
        s1 += __shfl_xor_sync(0xffffffffu, s1, 2);
        rs0[m] = s0; rs1[m] = s1;
    }
    if (tig == 0) {
        #pragma unroll
        for (int m = 0; m < 2; ++m) {
            #pragma unroll
            for (int rr = 0; rr < 2; ++rr) {
                int row = row0 + wid * 32 + m * 16 + grp + rr * 8;
                int mm = row & 255, nn_ = (row >> 8) & 255, b = row >> 16;
                float v = rr ? rs1[m] : rs0[m];
                d_scores[(((size_t)b * HH + h) * NN + nn_) * NN + mm] += v;
            }
        }
    }
}

// ---------------- 5. masked softmax ------------------------------------------
__global__ void k_softmax(const int* __restrict__ adj) {
    int bid = blockIdx.x;
    int n = bid % NN;
    int b = bid / (NN * HH);
    int m = threadIdx.x;
    float sc = d_scores[bid * NN + m];
    if (adj[(b * NN + n) * NN + m] == 0) sc = -1e9f;
    __shared__ float red[256];
    red[m] = sc; __syncthreads();
    for (int s = 128; s > 0; s >>= 1) { if (m < s) red[m] = fmaxf(red[m], red[m + s]); __syncthreads(); }
    float mx = red[0]; __syncthreads();
    float e = expf(sc - mx);
    red[m] = e; __syncthreads();
    for (int s = 128; s > 0; s >>= 1) { if (m < s) red[m] += red[m + s]; __syncthreads(); }
    d_scores[bid * NN + m] = e / red[0];
}

// ---------------- 6. attention mean over heads -------------------------------
__global__ void k_attn_mean() {
    int idx = blockIdx.x * 256 + threadIdx.x;
    int m = idx & 255, n = (idx >> 8) & 255, b = idx >> 16;
    float s = 0.f;
    #pragma unroll
    for (int h = 0; h < HH; ++h) s += d_scores[((b * HH + h) * NN + n) * NN + m];
    d_am[idx] = s * (1.f / HH);
}

// ---------------- 7. attn_out = attn @ V -------------------------------------
__global__ void k_attn_out() {
    int row = blockIdx.x;
    int b = row >> 8;
    int n = row & 255;
    __shared__ float sA[HH][NN];
    for (int i = threadIdx.x; i < HH * NN; i += 256) {
        int h = i >> 8, m = i & 255;
        sA[h][m] = d_scores[((b * HH + h) * NN + n) * NN + m];
    }
    __syncthreads();
    int c = threadIdx.x;
    int h = c >> 5;
    float acc = 0.f;
    #pragma unroll 4
    for (int m = 0; m < NN; ++m) acc += sA[h][m] * d_v[(b * NN + m) * HID + c];
    d_ao[row * HID + c] = acc;
}

// ---------------- 8. h_out = LN(residual + attn_out@Wo + bo) ------------------
__global__ void k_hout(const float* __restrict__ Wo, const float* __restrict__ bo,
                       const float* __restrict__ g1, const float* __restrict__ b1,
                       float* __restrict__ out) {
    int row = blockIdx.x;
    int c = threadIdx.x;
    __shared__ float s[HID];
    __shared__ float red[256];
    s[c] = d_ao[row * HID + c];
    __syncthreads();
    float acc = bo[c];
    #pragma unroll 4
    for (int k = 0; k < HID; ++k) acc += s[k] * Wo[k * HID + c];
    float y = acc + d_h[row * HID + c];
    red[c] = y; __syncthreads();
    for (int st = 128; st > 0; st >>= 1) { if (c < st) red[c] += red[c + st]; __syncthreads(); }
    float mean = red[0] * (1.f / HID); __syncthreads();
    float dlt = y - mean;
    red[c] = dlt * dlt; __syncthreads();
    for (int st = 128; st > 0; st >>= 1) { if (c < st) red[c] += red[c + st]; __syncthreads(); }
    float var = red[0] * (1.f / HID);
    out[row * HID + c] = (y - mean) * rsqrtf(var + LN_EPS) * g1[c] + b1[c];
}

// ---------------- 9. hp = h_out @ Weo (8 rows/block) --------------------------
__global__ void k_hp(const float* __restrict__ out, const float* __restrict__ Weo) {
    int r0 = blockIdx.x * 8;
    __shared__ float s[8][HID];
    for (int i = threadIdx.x; i < 8 * HID; i += 256)
        s[i >> 8][i & 255] = out[(r0 + (i >> 8)) * HID + (i & 255)];
    __syncthreads();
    int c = threadIdx.x;
    float acc[8];
    #pragma unroll
    for (int r = 0; r < 8; ++r) acc[r] = 0.f;
    #pragma unroll 2
    for (int k = 0; k < HID; ++k) {
        float w = Weo[k * EDGE_DIM + c];
        #pragma unroll
        for (int r = 0; r < 8; ++r) acc[r] += s[r][k] * w;
    }
    #pragma unroll
    for (int r = 0; r < 8; ++r) d_hp[(r0 + r) * EDGE_DIM + c] = acc[r];
}

// ---------------- 10. edge_out ------------------------------------------------
__global__ void k_edge_out(const float* __restrict__ E,
                           const float* __restrict__ beo,
                           const float* __restrict__ g2,
                           const float* __restrict__ b2,
                           float* __restrict__ out) {
    int w = blockIdx.x * 8 + (threadIdx.x >> 5);
    int lane = threadIdx.x & 31;
    int m = w & 255, n = (w >> 8) & 255, b = w >> 16;
    float am = d_am[w] * 0.5f;
    const float* Er = &E[(size_t)w * EDGE_DIM];
    const float* hn = &d_hp[(b * NN + n) * EDGE_DIM];
    const float* hm = &d_hp[(b * NN + m) * EDGE_DIM];
    float x[8];
    float s = 0.f, s2 = 0.f;
    #pragma unroll
    for (int j = 0; j < 8; ++j) {
        int c = j * 32 + lane;
        float v = Er[c] + am * (hn[c] + hm[c]) + beo[c];
        x[j] = v; s += v; s2 += v * v;
    }
    #pragma unroll
    for (int o = 16; o > 0; o >>= 1) {
        s  += __shfl_xor_sync(0xffffffffu, s,  o);
        s2 += __shfl_xor_sync(0xffffffffu, s2, o);
    }
    float mean = s * (1.f / EDGE_DIM);
    float var  = s2 * (1.f / EDGE_DIM) - mean * mean;
    float rinv = rsqrtf(var + LN_EPS);
    float* op = &out[OUT_EDGE_BASE + (size_t)w * EDGE_DIM];
    #pragma unroll
    for (int j = 0; j < 8; ++j) {
        int c = j * 32 + lane;
        op[c] = (x[j] - mean) * rinv * g2[c] + b2[c];
    }
}

// ---------------- launch ------------------------------------------------------
extern "C" void kernel_launch(void* const* d_in, const int* in_sizes, int n_in,
                              void* d_out, int out_size) {
    const float* node = (const float*)d_in[0];
    const float* E    = (const float*)d_in[1];
    const int*   adj  = (const int*)  d_in[2];
    const float* Wn  = (const float*)d_in[3];  const float* bn  = (const float*)d_in[4];
    const float* Wq  = (const float*)d_in[5];  const float* bq  = (const float*)d_in[6];
    const float* Wk  = (const float*)d_in[7];  const float* bk  = (const float*)d_in[8];
    const float* Wv  = (const float*)d_in[9];  const float* bv  = (const float*)d_in[10];
    const float* Wep = (const float*)d_in[11]; const float* bep = (const float*)d_in[12];
    const float* Weg = (const float*)d_in[13]; const float* beg = (const float*)d_in[14];
    const float* Wo  = (const float*)d_in[15]; const float* bo  = (const float*)d_in[16];
    const float* Weo = (const float*)d_in[17]; const float* beo = (const float*)d_in[18];
    const float* g1  = (const float*)d_in[19]; const float* b1  = (const float*)d_in[20];
    const float* g2  = (const float*)d_in[21]; const float* b2  = (const float*)d_in[22];
    float* out = (float*)d_out;

    cudaFuncSetAttribute(k_edge_attn_mma,
                         cudaFuncAttributeMaxDynamicSharedMemorySize, SMEM_BYTES);

    k_wT        <<<dim3(8, 8, 2), dim3(32, 32)>>>(Wep, Weg);
    k_node_proj <<<BB*NN/8, 256>>>(node, Wn, bn);
    k_qkv       <<<BB*NN/8, 256>>>(Wq, bq, Wk, bk, Wv, bv);
    k_scores    <<<BB*HH*NN, NN>>>();
    k_edge_attn_mma<<<dim3(HH, BB*NN*NN/256), 256, SMEM_BYTES>>>(E, bep, beg);
    k_softmax   <<<BB*HH*NN, NN>>>(adj);
    k_attn_mean <<<BB*NN*NN/256, 256>>>();
    k_attn_out  <<<BB*NN, HID>>>();
    k_hout      <<<BB*NN, HID>>>(Wo, bo, g1, b1, out);
    k_hp        <<<BB*NN/8, 256>>>(out, Weo);
    k_edge_out  <<<BB*NN*NN/8, 256>>>(E, beo, g2, b2, out);
}

// round 6
// speedup vs baseline: 2.4838x; 1.1741x over previous
#include <cuda_runtime.h>
#include <cstdint>
#include <math.h>

#define BB 2
#define NN 256
#define NODE_DIM 128
#define EDGE_DIM 256
#define HID 256
#define HH 8
#define DD 32
#define LN_EPS 1e-5f
#define OUT_EDGE_BASE (BB*NN*HID)

// ---------------- scratch (device globals) ----------------------------------
__device__ float d_h [BB*NN*HID];
__device__ float d_q [BB*NN*HID];
__device__ float d_k [BB*NN*HID];
__device__ float d_v [BB*NN*HID];
__device__ float d_scores[BB*HH*NN*NN];
__device__ float d_am[BB*NN*NN];
__device__ float d_ao[BB*NN*HID];
__device__ float d_hp[BB*NN*HID];
__device__ __align__(16) float d_WpT[HID*EDGE_DIM];   // [n][perm(k)], tf32 bits
__device__ __align__(16) float d_WgT[HID*EDGE_DIM];   // [n][perm(k)], tf32 bits

// ---------------- PTX helpers ------------------------------------------------
__device__ __forceinline__ uint32_t smem_u32(const void* p) {
    uint32_t a;
    asm("{ .reg .u64 t; cvta.to.shared.u64 t, %1; cvt.u32.u64 %0, t; }" : "=r"(a) : "l"(p));
    return a;
}
__device__ __forceinline__ void cp_async16(uint32_t dst, const void* src) {
    asm volatile("cp.async.cg.shared.global [%0], [%1], 16;" :: "r"(dst), "l"(src));
}
#define CP_COMMIT() asm volatile("cp.async.commit_group;" ::: "memory")
#define CP_WAIT(n)  asm volatile("cp.async.wait_group %0;" :: "n"(n) : "memory")

__device__ __forceinline__ void mma_tf32(float d[4], const uint32_t a[4],
                                         uint32_t b0, uint32_t b1) {
    asm volatile(
        "mma.sync.aligned.m16n8k8.row.col.f32.tf32.tf32.f32 "
        "{%0,%1,%2,%3}, {%4,%5,%6,%7}, {%8,%9}, {%0,%1,%2,%3};"
        : "+f"(d[0]), "+f"(d[1]), "+f"(d[2]), "+f"(d[3])
        : "r"(a[0]), "r"(a[1]), "r"(a[2]), "r"(a[3]), "r"(b0), "r"(b1));
}

// ---------------- 0. weight transpose + tf32 round + fragment-pair packing ----
// Pack so (k, k+4) within each 8-group are adjacent: kk=k%8 -> kk<4 ? 2kk : 2(kk-4)+1
__global__ void k_wT(const float* __restrict__ Wep, const float* __restrict__ Weg) {
    __shared__ float t[32][33];
    const float* W = blockIdx.z ? Weg : Wep;
    float* O = blockIdx.z ? d_WgT : d_WpT;
    int n0 = blockIdx.x * 32, k0 = blockIdx.y * 32;
    t[threadIdx.y][threadIdx.x] = W[(k0 + threadIdx.y) * EDGE_DIM + n0 + threadIdx.x];
    __syncthreads();
    float v = t[threadIdx.x][threadIdx.y];      // = W[k0+tx][n0+ty]
    uint32_t u;
    asm("cvt.rna.tf32.f32 %0, %1;" : "=r"(u) : "f"(v));
    int k = k0 + threadIdx.x;
    int pk = (k & ~7) | (((k & 3) << 1) | ((k >> 2) & 1));
    O[(n0 + threadIdx.y) * EDGE_DIM + pk] = __uint_as_float(u);
}

// ---------------- 1. h = node @ Wn + bn (8 rows/block) -----------------------
__global__ void k_node_proj(const float* __restrict__ node,
                            const float* __restrict__ Wn,
                            const float* __restrict__ bn) {
    int r0 = blockIdx.x * 8;
    __shared__ float s[8][NODE_DIM];
    for (int i = threadIdx.x; i < 8 * NODE_DIM; i += 256)
        s[i >> 7][i & 127] = node[(r0 + (i >> 7)) * NODE_DIM + (i & 127)];
    __syncthreads();
    int c = threadIdx.x;
    float acc[8]; float bb = bn[c];
    #pragma unroll
    for (int r = 0; r < 8; ++r) acc[r] = bb;
    #pragma unroll 4
    for (int k = 0; k < NODE_DIM; ++k) {
        float w = Wn[k * HID + c];
        #pragma unroll
        for (int r = 0; r < 8; ++r) acc[r] += s[r][k] * w;
    }
    #pragma unroll
    for (int r = 0; r < 8; ++r) d_h[(r0 + r) * HID + c] = acc[r];
}

// ---------------- 2. Q,K,V (8 rows/block) ------------------------------------
__global__ void k_qkv(const float* __restrict__ Wq, const float* __restrict__ bq,
                      const float* __restrict__ Wk, const float* __restrict__ bk,
                      const float* __restrict__ Wv, const float* __restrict__ bv) {
    int r0 = blockIdx.x * 8;
    __shared__ float s[8][HID];
    for (int i = threadIdx.x; i < 8 * HID; i += 256)
        s[i >> 8][i & 255] = d_h[(r0 + (i >> 8)) * HID + (i & 255)];
    __syncthreads();
    int c = threadIdx.x;
    float aq[8], ak[8], av[8];
    float bq0 = bq[c], bk0 = bk[c], bv0 = bv[c];
    #pragma unroll
    for (int r = 0; r < 8; ++r) { aq[r] = bq0; ak[r] = bk0; av[r] = bv0; }
    #pragma unroll 2
    for (int k = 0; k < HID; ++k) {
        float wq = Wq[k * HID + c], wk = Wk[k * HID + c], wv = Wv[k * HID + c];
        #pragma unroll
        for (int r = 0; r < 8; ++r) {
            float e = s[r][k];
            aq[r] += e * wq; ak[r] += e * wk; av[r] += e * wv;
        }
    }
    #pragma unroll
    for (int r = 0; r < 8; ++r) {
        d_q[(r0 + r) * HID + c] = aq[r];
        d_k[(r0 + r) * HID + c] = ak[r];
        d_v[(r0 + r) * HID + c] = av[r];
    }
}

// ---------------- 3. scores = QK^T / sqrt(D) — smem-tiled, coalesced ----------
#define KS_PAD 36
__global__ void k_scores() {
    // blockIdx.x = ((b*HH + h) << 2) | nt
    int nt = blockIdx.x & 3;
    int h  = (blockIdx.x >> 2) & 7;
    int b  = blockIdx.x >> 5;
    __shared__ float sQ[64][KS_PAD];
    __shared__ float sK[256][KS_PAD];
    int tid = threadIdx.x;
    #pragma unroll
    for (int i = 0; i < 32; ++i) {
        int idx = tid + i * 256;
        int r = idx >> 5, c = idx & 31;
        sK[r][c] = d_k[(b * NN + r) * HID + h * DD + c];
    }
    #pragma unroll
    for (int i = 0; i < 8; ++i) {
        int idx = tid + i * 256;
        int r = idx >> 5, c = idx & 31;
        sQ[r][c] = d_q[(b * NN + nt * 64 + r) * HID + h * DD + c];
    }
    __syncthreads();
    int nl = tid >> 2, q = tid & 3;
    float qr[32];
    #pragma unroll
    for (int d = 0; d < 32; ++d) qr[d] = sQ[nl][d];
    float* dst = &d_scores[(((size_t)b * HH + h) * NN + nt * 64 + nl) * NN];
    #pragma unroll 4
    for (int i = 0; i < 64; ++i) {
        int m = i * 4 + q;
        float acc = 0.f;
        #pragma unroll
        for (int d = 0; d < 32; ++d) acc += qr[d] * sK[m][d];
        dst[m] = acc * 0.17677669529663687f;
    }
}

// ---------------- 4. edge bias via mma.sync tf32 ------------------------------
#define SA_STRIDE 36
#define SA_BUF    (256*SA_STRIDE)          // 9216 floats / buffer
#define OFF_BP    (2*SA_BUF)               // 18432
#define SB_STRIDE 264
#define OFF_BG    (OFF_BP + 32*SB_STRIDE)  // 26880
#define OFF_BIAS  (OFF_BG + 32*SB_STRIDE)  // 35328
#define SMEM_FLOATS (OFF_BIAS + 64)
#define SMEM_BYTES  (SMEM_FLOATS*4)

__global__ void __launch_bounds__(256, 1)
k_edge_attn_mma(const float* __restrict__ E,
                const float* __restrict__ bep, const float* __restrict__ beg) {
    extern __shared__ float sm[];
    const int tid = threadIdx.x;
    const int wid = tid >> 5, lane = tid & 31;
    const int tig = lane & 3, grp = lane >> 2;
    const int h = blockIdx.x;
    const int row0 = blockIdx.y * 256;

    float* sBp = sm + OFF_BP;
    float* sBg = sm + OFF_BG;
    float* sbias = sm + OFF_BIAS;
    uint32_t sA_addr = smem_u32(sm);

    // one-time: head's (packed) weight slices + biases into smem
    #pragma unroll
    for (int i = 0; i < 8; ++i) {
        int lin = tid + i * 256;
        int n = lin >> 6, q = lin & 63;
        *(float4*)&sBp[n * SB_STRIDE + q * 4] =
            *(const float4*)&d_WpT[(h * 32 + n) * EDGE_DIM + q * 4];
        *(float4*)&sBg[n * SB_STRIDE + q * 4] =
            *(const float4*)&d_WgT[(h * 32 + n) * EDGE_DIM + q * 4];
    }
    if (tid < 32) {
        sbias[tid]      = bep[h * 32 + tid];
        sbias[32 + tid] = beg[h * 32 + tid];
    }

    float d[2][8][4];
    #pragma unroll
    for (int m = 0; m < 2; ++m)
        #pragma unroll
        for (int j = 0; j < 8; ++j)
            #pragma unroll
            for (int e = 0; e < 4; ++e) d[m][j][e] = 0.f;

    // prefetch chunk 0
    {
        #pragma unroll
        for (int i = 0; i < 8; ++i) {
            int lin = tid + i * 256;
            int r = lin >> 3, q = lin & 7;
            cp_async16(sA_addr + (r * SA_STRIDE + q * 4) * 4,
                       &E[(size_t)(row0 + r) * EDGE_DIM + q * 4]);
        }
        CP_COMMIT();
    }

    #pragma unroll 1
    for (int c = 0; c < 8; ++c) {
        int buf = c & 1;
        if (c < 7) {
            int nb = buf ^ 1;
            #pragma unroll
            for (int i = 0; i < 8; ++i) {
                int lin = tid + i * 256;
                int r = lin >> 3, q = lin & 7;
                cp_async16(sA_addr + (nb * SA_BUF + r * SA_STRIDE + q * 4) * 4,
                           &E[(size_t)(row0 + r) * EDGE_DIM + (c + 1) * 32 + q * 4]);
            }
            CP_COMMIT();
            CP_WAIT(1);
        } else {
            CP_WAIT(0);
        }
        __syncthreads();

        const float* Ab = sm + buf * SA_BUF + (wid * 32) * SA_STRIDE;
        #pragma unroll
        for (int k8 = 0; k8 < 4; ++k8) {
            int kA = k8 * 8 + tig;
            uint32_t a[2][4];
            #pragma unroll
            for (int m = 0; m < 2; ++m) {
                int rb = (m * 16 + grp) * SA_STRIDE;
                a[m][0] = __float_as_uint(Ab[rb + kA]);
                a[m][1] = __float_as_uint(Ab[rb + 8 * SA_STRIDE + kA]);
                a[m][2] = __float_as_uint(Ab[rb + kA + 4]);
                a[m][3] = __float_as_uint(Ab[rb + 8 * SA_STRIDE + kA + 4]);
            }
            int kBp = c * 32 + k8 * 8 + tig * 2;   // packed (k,k+4) pair offset
            #pragma unroll
            for (int j = 0; j < 8; ++j) {
                const float* Bm = (j < 4) ? sBp : sBg;
                int nb = ((j & 3) * 8 + grp) * SB_STRIDE;
                float2 bb = *(const float2*)&Bm[nb + kBp];
                uint32_t b0 = __float_as_uint(bb.x), b1 = __float_as_uint(bb.y);
                mma_tf32(d[0][j], a[0], b0, b1);
                mma_tf32(d[1][j], a[1], b0, b1);
            }
        }
        __syncthreads();
    }

    // epilogue: bias + sigmoid + gated reduce over the head's 32 dims
    float rs0[2], rs1[2];
    #pragma unroll
    for (int m = 0; m < 2; ++m) {
        float s0 = 0.f, s1 = 0.f;
        #pragma unroll
        for (int j = 0; j < 4; ++j) {
            #pragma unroll
            for (int e = 0; e < 2; ++e) {
                int cl = j * 8 + tig * 2 + e;
                float bp = sbias[cl], bg = sbias[32 + cl];
                float p0 = d[m][j][e]     + bp;
                float g0 = d[m][j + 4][e] + bg;
                s0 += p0 / (1.f + expf(-g0));
                float p1 = d[m][j][e + 2]     + bp;
                float g1 = d[m][j + 4][e + 2] + bg;
                s1 += p1 / (1.f + expf(-g1));
            }
        }
        s0 += __shfl_xor_sync(0xffffffffu, s0, 1);
        s0 += __shfl_xor_sync(0xffffffffu, s0, 2);
        s1 += __shfl_xor_sync(0xffffffffu, s1, 1);
        s1 += __shfl_xor_sync(0xffffffffu, s1, 2);
        rs0[m] = s0; rs1[m] = s1;
    }
    if (tig == 0) {
        #pragma unroll
        for (int m = 0; m < 2; ++m) {
            #pragma unroll
            for (int rr = 0; rr < 2; ++rr) {
                int row = row0 + wid * 32 + m * 16 + grp + rr * 8;
                int mm = row & 255, nn_ = (row >> 8) & 255, b = row >> 16;
                float v = rr ? rs1[m] : rs0[m];
                d_scores[(((size_t)b * HH + h) * NN + nn_) * NN + mm] += v;
            }
        }
    }
}

// ---------------- 5. masked softmax ------------------------------------------
__global__ void k_softmax(const int* __restrict__ adj) {
    int bid = blockIdx.x;
    int n = bid % NN;
    int b = bid / (NN * HH);
    int m = threadIdx.x;
    float sc = d_scores[bid * NN + m];
    if (adj[(b * NN + n) * NN + m] == 0) sc = -1e9f;
    __shared__ float red[256];
    red[m] = sc; __syncthreads();
    for (int s = 128; s > 0; s >>= 1) { if (m < s) red[m] = fmaxf(red[m], red[m + s]); __syncthreads(); }
    float mx = red[0]; __syncthreads();
    float e = expf(sc - mx);
    red[m] = e; __syncthreads();
    for (int s = 128; s > 0; s >>= 1) { if (m < s) red[m] += red[m + s]; __syncthreads(); }
    d_scores[bid * NN + m] = e / red[0];
}

// ---------------- 6+7. attn_out = attn @ V  (+ fused head-mean) ---------------
__global__ void k_attn_out() {
    int blk = blockIdx.x;                 // 128 blocks: b * 64 + ntile
    int b = blk >> 6;
    int n0 = (blk & 63) * 4;
    __shared__ float sA[4][HH][NN];       // 32KB
    for (int i = threadIdx.x; i < 4 * HH * NN; i += 256) {
        int r = i >> 11, h = (i >> 8) & 7, m = i & 255;
        sA[r][h][m] = d_scores[(((size_t)b * HH + h) * NN + n0 + r) * NN + m];
    }
    __syncthreads();
    // fused attention mean over heads
    for (int i = threadIdx.x; i < 4 * NN; i += 256) {
        int r = i >> 8, m = i & 255;
        float s = 0.f;
        #pragma unroll
        for (int h2 = 0; h2 < HH; ++h2) s += sA[r][h2][m];
        d_am[(b * NN + n0 + r) * NN + m] = s * (1.f / HH);
    }
    int c = threadIdx.x;
    int h = c >> 5;
    float acc[4] = {0.f, 0.f, 0.f, 0.f};
    #pragma unroll 4
    for (int m = 0; m < NN; ++m) {
        float v = d_v[(b * NN + m) * HID + c];
        #pragma unroll
        for (int r = 0; r < 4; ++r) acc[r] += sA[r][h][m] * v;
    }
    #pragma unroll
    for (int r = 0; r < 4; ++r) d_ao[(b * NN + n0 + r) * HID + c] = acc[r];
}

// ---------------- 8. h_out = LN(residual + attn_out@Wo + bo) ------------------
__global__ void k_hout(const float* __restrict__ Wo, const float* __restrict__ bo,
                       const float* __restrict__ g1, const float* __restrict__ b1,
                       float* __restrict__ out) {
    int row = blockIdx.x;
    int c = threadIdx.x;
    __shared__ float s[HID];
    __shared__ float red[256];
    s[c] = d_ao[row * HID + c];
    __syncthreads();
    float acc = bo[c];
    #pragma unroll 4
    for (int k = 0; k < HID; ++k) acc += s[k] * Wo[k * HID + c];
    float y = acc + d_h[row * HID + c];
    red[c] = y; __syncthreads();
    for (int st = 128; st > 0; st >>= 1) { if (c < st) red[c] += red[c + st]; __syncthreads(); }
    float mean = red[0] * (1.f / HID); __syncthreads();
    float dlt = y - mean;
    red[c] = dlt * dlt; __syncthreads();
    for (int st = 128; st > 0; st >>= 1) { if (c < st) red[c] += red[c + st]; __syncthreads(); }
    float var = red[0] * (1.f / HID);
    out[row * HID + c] = (y - mean) * rsqrtf(var + LN_EPS) * g1[c] + b1[c];
}

// ---------------- 9. hp = h_out @ Weo (8 rows/block) --------------------------
__global__ void k_hp(const float* __restrict__ out, const float* __restrict__ Weo) {
    int r0 = blockIdx.x * 8;
    __shared__ float s[8][HID];
    for (int i = threadIdx.x; i < 8 * HID; i += 256)
        s[i >> 8][i & 255] = out[(r0 + (i >> 8)) * HID + (i & 255)];
    __syncthreads();
    int c = threadIdx.x;
    float acc[8];
    #pragma unroll
    for (int r = 0; r < 8; ++r) acc[r] = 0.f;
    #pragma unroll 2
    for (int k = 0; k < HID; ++k) {
        float w = Weo[k * EDGE_DIM + c];
        #pragma unroll
        for (int r = 0; r < 8; ++r) acc[r] += s[r][k] * w;
    }
    #pragma unroll
    for (int r = 0; r < 8; ++r) d_hp[(r0 + r) * EDGE_DIM + c] = acc[r];
}

// ---------------- 10. edge_out ------------------------------------------------
__global__ void k_edge_out(const float* __restrict__ E,
                           const float* __restrict__ beo,
                           const float* __restrict__ g2,
                           const float* __restrict__ b2,
                           float* __restrict__ out) {
    int w = blockIdx.x * 8 + (threadIdx.x >> 5);
    int lane = threadIdx.x & 31;
    int m = w & 255, n = (w >> 8) & 255, b = w >> 16;
    float am = d_am[w] * 0.5f;
    const float* Er = &E[(size_t)w * EDGE_DIM];
    const float* hn = &d_hp[(b * NN + n) * EDGE_DIM];
    const float* hm = &d_hp[(b * NN + m) * EDGE_DIM];
    float x[8];
    float s = 0.f, s2 = 0.f;
    #pragma unroll
    for (int j = 0; j < 8; ++j) {
        int c = j * 32 + lane;
        float v = Er[c] + am * (hn[c] + hm[c]) + beo[c];
        x[j] = v; s += v; s2 += v * v;
    }
    #pragma unroll
    for (int o = 16; o > 0; o >>= 1) {
        s  += __shfl_xor_sync(0xffffffffu, s,  o);
        s2 += __shfl_xor_sync(0xffffffffu, s2, o);
    }
    float mean = s * (1.f / EDGE_DIM);
    float var  = s2 * (1.f / EDGE_DIM) - mean * mean;
    float rinv = rsqrtf(var + LN_EPS);
    float* op = &out[OUT_EDGE_BASE + (size_t)w * EDGE_DIM];
    #pragma unroll
    for (int j = 0; j < 8; ++j) {
        int c = j * 32 + lane;
        op[c] = (x[j] - mean) * rinv * g2[c] + b2[c];
    }
}

// ---------------- launch ------------------------------------------------------
extern "C" void kernel_launch(void* const* d_in, const int* in_sizes, int n_in,
                              void* d_out, int out_size) {
    const float* node = (const float*)d_in[0];
    const float* E    = (const float*)d_in[1];
    const int*   adj  = (const int*)  d_in[2];
    const float* Wn  = (const float*)d_in[3];  const float* bn  = (const float*)d_in[4];
    const float* Wq  = (const float*)d_in[5];  const float* bq  = (const float*)d_in[6];
    const float* Wk  = (const float*)d_in[7];  const float* bk  = (const float*)d_in[8];
    const float* Wv  = (const float*)d_in[9];  const float* bv  = (const float*)d_in[10];
    const float* Wep = (const float*)d_in[11]; const float* bep = (const float*)d_in[12];
    const float* Weg = (const float*)d_in[13]; const float* beg = (const float*)d_in[14];
    const float* Wo  = (const float*)d_in[15]; const float* bo  = (const float*)d_in[16];
    const float* Weo = (const float*)d_in[17]; const float* beo = (const float*)d_in[18];
    const float* g1  = (const float*)d_in[19]; const float* b1  = (const float*)d_in[20];
    const float* g2  = (const float*)d_in[21]; const float* b2  = (const float*)d_in[22];
    float* out = (float*)d_out;

    cudaFuncSetAttribute(k_edge_attn_mma,
                         cudaFuncAttributeMaxDynamicSharedMemorySize, SMEM_BYTES);

    k_wT        <<<dim3(8, 8, 2), dim3(32, 32)>>>(Wep, Weg);
    k_node_proj <<<BB*NN/8, 256>>>(node, Wn, bn);
    k_qkv       <<<BB*NN/8, 256>>>(Wq, bq, Wk, bk, Wv, bv);
    k_scores    <<<BB*HH*4, 256>>>();
    k_edge_attn_mma<<<dim3(HH, BB*NN*NN/256), 256, SMEM_BYTES>>>(E, bep, beg);
    k_softmax   <<<BB*HH*NN, NN>>>(adj);
    k_attn_out  <<<BB*64, 256>>>();
    k_hout      <<<BB*NN, HID>>>(Wo, bo, g1, b1, out);
    k_hp        <<<BB*NN/8, 256>>>(out, Weo);
    k_edge_out  <<<BB*NN*NN/8, 256>>>(E, beo, g2, b2, out);
}